// round 13
// baseline (speedup 1.0000x reference)
#include <cuda_runtime.h>
#include <math.h>
#include <stdint.h>

// ---------------- problem constants ----------------
#define BB    2
#define QQN   4
#define NH    32
#define NHK   8
#define HD    128
#define DMODEL 4096
#define KVLEN 4096
#define STOT  4100          // KVLEN + QQN
#define RSEL  410           // max(128, 4100 - int(4100*0.9))
#define NCTOT 6144          // 4096 (q) + 1024 (k) + 1024 (v)
#define PKC   32            // proj split-K chunks (chunk = 128)
#define OKC   32            // out-proj split-K chunks (chunk = 128)

#define ROPE_BLOCKS 1025    // ceil(STOT*64 / 256)
#define PROJ_TILES  6       // 6144 cols / 1024
#define PROJ_KC     32

// ---------------- device scratch ----------------
__device__ float g_cos[STOT * 64];
__device__ float g_sin[STOT * 64];
__device__ float g_pp[PKC][8][NCTOT];          // projection partials
__device__ float g_qrope[BB * NH * QQN * HD];  // roped queries
__device__ float g_knew[BB * NHK * QQN * HD];  // roped new keys
__device__ float g_vnew[BB * NHK * QQN * HD];  // new values (raw)
__device__ float g_scores[(size_t)BB * NH * QQN * STOT];
__device__ float g_attn[BB * QQN * DMODEL];    // [b][q][h*HD+d]
__device__ float g_op[OKC][8][DMODEL];         // out-proj partials

// ---------------- 1) fused: rope tables + QKV projection --------------------
// blocks [0, ROPE_BLOCKS): rope table; blocks [ROPE_BLOCKS, +192): projection.
// Independent work, overlapped in one launch.
__global__ void __launch_bounds__(256) rope_proj_kernel(
        const float* __restrict__ hidden,
        const float* __restrict__ Wq,
        const float* __restrict__ Wk,
        const float* __restrict__ Wv) {
    int bid = blockIdx.x;
    int tid = threadIdx.x;

    if (bid < ROPE_BLOCKS) {
        // ---- rope table (numerics: identical fp32 chain to reference) ----
        int i = bid * 256 + tid;
        if (i < STOT * 64) {
            int p = i >> 6;
            int j = i & 63;
            float expo = (float)(2 * j) / 128.0f;   // exact
            float invf = 1.0f / powf(10000.0f, expo);
            float ang = (float)p * invf;
            g_cos[i] = cosf(ang);
            g_sin[i] = sinf(ang);
        }
        return;
    }

    // ---- QKV projection: 1024-col tile, 128-row k-chunk, split-K partials ----
    __shared__ float hs[8][128];
    int pb   = bid - ROPE_BLOCKS;
    int tile = pb % PROJ_TILES;      // 0..5
    int kc   = pb / PROJ_TILES;      // 0..31
    int k0   = kc * 128;

    {
        int f = tid * 4;             // 256 threads x float4 = 1024 floats
        int m = f >> 7;
        int d = f & 127;
        *(float4*)&hs[m][d] = *(const float4*)&hidden[m * DMODEL + k0 + d];
    }
    __syncthreads();

    const float* W;
    int ld, colbase;
    if (tile < 4)      { W = Wq; ld = 4096; colbase = tile * 1024; }
    else if (tile == 4){ W = Wk; ld = 1024; colbase = 0; }
    else               { W = Wv; ld = 1024; colbase = 0; }

    int wcol = colbase + tid * 4;
    const float* Wp = W + (size_t)k0 * ld + wcol;

    float4 a[8];
    #pragma unroll
    for (int m = 0; m < 8; m++) { a[m].x = 0.f; a[m].y = 0.f; a[m].z = 0.f; a[m].w = 0.f; }

    #pragma unroll 4
    for (int d = 0; d < 128; d++) {
        float4 wv = *(const float4*)(Wp + (size_t)d * ld);
        #pragma unroll
        for (int m = 0; m < 8; m++) {
            float h = hs[m][d];
            a[m].x = fmaf(h, wv.x, a[m].x);
            a[m].y = fmaf(h, wv.y, a[m].y);
            a[m].z = fmaf(h, wv.z, a[m].z);
            a[m].w = fmaf(h, wv.w, a[m].w);
        }
    }

    int gc = tile * 1024 + tid * 4;
    #pragma unroll
    for (int m = 0; m < 8; m++)
        *(float4*)&g_pp[kc][m][gc] = a[m];
}

// ---------------- 2) reduce partials + rope q / new-k (float4) --------------
__global__ void __launch_bounds__(256) proj_reduce_kernel() {
    int idx = blockIdx.x * blockDim.x + threadIdx.x;   // 12288 threads
    if (idx >= 8 * (NCTOT / 4)) return;
    int c4 = (idx % (NCTOT / 4)) * 4;
    int m  = idx / (NCTOT / 4);

    float4 s = make_float4(0.f, 0.f, 0.f, 0.f);
    #pragma unroll
    for (int k = 0; k < PKC; k++) {
        float4 v = *(const float4*)&g_pp[k][m][c4];
        s.x += v.x; s.y += v.y; s.z += v.z; s.w += v.w;
    }

    int b  = m >> 2;
    int qq = m & 3;
    int d0 = c4 & 127;

    if (c4 < 5120) {  // q or k_new: rope at position 4096+qq (4 dims, same side)
        int pc4 = (d0 < 64) ? c4 + 64 : c4 - 64;
        float4 s2 = make_float4(0.f, 0.f, 0.f, 0.f);
        #pragma unroll
        for (int k = 0; k < PKC; k++) {
            float4 v = *(const float4*)&g_pp[k][m][pc4];
            s2.x += v.x; s2.y += v.y; s2.z += v.z; s2.w += v.w;
        }
        int p = KVLEN + qq;
        float4 ct = *(const float4*)&g_cos[p * 64 + (d0 & 63)];
        float4 st = *(const float4*)&g_sin[p * 64 + (d0 & 63)];
        float sg = (d0 < 64) ? -1.0f : 1.0f;
        float4 r;
        r.x = s.x * ct.x + sg * s2.x * st.x;
        r.y = s.y * ct.y + sg * s2.y * st.y;
        r.z = s.z * ct.z + sg * s2.z * st.z;
        r.w = s.w * ct.w + sg * s2.w * st.w;
        if (c4 < 4096) {
            int h = c4 >> 7;
            *(float4*)&g_qrope[(((b * NH + h) * QQN) + qq) * HD + d0] = r;
        } else {
            int hk = (c4 - 4096) >> 7;
            *(float4*)&g_knew[(((b * NHK + hk) * QQN) + qq) * HD + d0] = r;
        }
    } else {          // v_new: raw copy
        int hk = (c4 - 5120) >> 7;
        *(float4*)&g_vnew[(((b * NHK + hk) * QQN) + qq) * HD + d0] = s;
    }
}

// ---------------- 3) draft scores -------------------------------------------
// 16 lanes per key, 2 keys per warp (9 shfl/key), NO manual prefetch buffer
// (register pressure was the R6 killer); unroll 4 supplies MLP instead.
__device__ __forceinline__ void reduce_store_2key(
    float acc0, float acc1, float acc2, float acc3,
    int l, float* __restrict__ sb, int jbase)
{
    acc0 += __shfl_xor_sync(0xffffffffu, acc0, 4);
    acc1 += __shfl_xor_sync(0xffffffffu, acc1, 4);
    acc2 += __shfl_xor_sync(0xffffffffu, acc2, 4);
    acc3 += __shfl_xor_sync(0xffffffffu, acc3, 4);
    acc0 += __shfl_xor_sync(0xffffffffu, acc0, 8);
    acc1 += __shfl_xor_sync(0xffffffffu, acc1, 8);
    acc2 += __shfl_xor_sync(0xffffffffu, acc2, 8);
    acc3 += __shfl_xor_sync(0xffffffffu, acc3, 8);
    int qi = (l >> 2) & 3;
    float w = (qi == 0) ? acc0 : (qi == 1) ? acc1 : (qi == 2) ? acc2 : acc3;
    w += __shfl_xor_sync(0xffffffffu, w, 1);
    w += __shfl_xor_sync(0xffffffffu, w, 2);
    if ((l & 3) == 0)
        sb[(size_t)qi * STOT + jbase + (l >> 4)] = w;
}

__device__ __forceinline__ float dot8(float4 a0, float4 a1, float4 b0, float4 b1) {
    float s = a0.x * b0.x;
    s = fmaf(a0.y, b0.y, s);
    s = fmaf(a0.z, b0.z, s);
    s = fmaf(a0.w, b0.w, s);
    s = fmaf(a1.x, b1.x, s);
    s = fmaf(a1.y, b1.y, s);
    s = fmaf(a1.z, b1.z, s);
    s = fmaf(a1.w, b1.w, s);
    return s;
}

__global__ void __launch_bounds__(256) score_kernel(const float* __restrict__ kcache) {
    int bh = blockIdx.x;              // 0..63
    int b  = bh >> 5;
    int h  = bh & 31;
    int ks = blockIdx.y;              // 0..7 -> 512 cache keys each
    int tid = threadIdx.x;
    int w = tid >> 5;
    int l = tid & 31;
    int g  = l >> 4;                  // which of the warp's 2 keys
    int sl = l & 15;                  // sublane within key group
    int d0 = sl * 8;                  // first of this lane's 8 dims
    int cidx = (l & 7) * 8;           // cos/sin base index (d0 & 63)
    float sg = (sl < 8) ? -1.0f : 1.0f;

    // q: 4 queries x 8 dims in registers (no LDS/LDG in loop)
    const float* qb = g_qrope + (size_t)bh * QQN * HD;
    float4 qA[4], qB[4];
    #pragma unroll
    for (int qi = 0; qi < 4; qi++) {
        qA[qi] = *(const float4*)(qb + qi * HD + d0);
        qB[qi] = *(const float4*)(qb + qi * HD + d0 + 4);
    }

    const float* kb = kcache + (size_t)bh * KVLEN * HD;
    float* sb = g_scores + (size_t)bh * QQN * STOT;

    int j0 = ks * 512;

    #pragma unroll 4
    for (int t = 0; t < 32; t++) {
        int jbase = j0 + 2 * w + 16 * t;
        const float* kp = kb + (size_t)(jbase + g) * HD + d0;
        const float* cp = &g_cos[(jbase + g) * 64 + cidx];
        const float* sp = &g_sin[(jbase + g) * 64 + cidx];
        float4 kA = *(const float4*)kp;
        float4 kB = *(const float4*)(kp + 4);
        float4 cA = *(const float4*)cp;
        float4 cB = *(const float4*)(cp + 4);
        float4 sA = *(const float4*)sp;
        float4 sB = *(const float4*)(sp + 4);

        // RoPE partner exchange (dim +-64 lives at lane^8)
        float pAx = __shfl_xor_sync(0xffffffffu, kA.x, 8);
        float pAy = __shfl_xor_sync(0xffffffffu, kA.y, 8);
        float pAz = __shfl_xor_sync(0xffffffffu, kA.z, 8);
        float pAw = __shfl_xor_sync(0xffffffffu, kA.w, 8);
        float pBx = __shfl_xor_sync(0xffffffffu, kB.x, 8);
        float pBy = __shfl_xor_sync(0xffffffffu, kB.y, 8);
        float pBz = __shfl_xor_sync(0xffffffffu, kB.z, 8);
        float pBw = __shfl_xor_sync(0xffffffffu, kB.w, 8);

        float4 krA, krB;
        krA.x = fmaf(kA.x, cA.x, sg * pAx * sA.x);
        krA.y = fmaf(kA.y, cA.y, sg * pAy * sA.y);
        krA.z = fmaf(kA.z, cA.z, sg * pAz * sA.z);
        krA.w = fmaf(kA.w, cA.w, sg * pAw * sA.w);
        krB.x = fmaf(kB.x, cB.x, sg * pBx * sB.x);
        krB.y = fmaf(kB.y, cB.y, sg * pBy * sB.y);
        krB.z = fmaf(kB.z, cB.z, sg * pBz * sB.z);
        krB.w = fmaf(kB.w, cB.w, sg * pBw * sB.w);

        float a0 = dot8(krA, krB, qA[0], qB[0]);
        float a1 = dot8(krA, krB, qA[1], qB[1]);
        float a2 = dot8(krA, krB, qA[2], qB[2]);
        float a3 = dot8(krA, krB, qA[3], qB[3]);
        reduce_store_2key(a0, a1, a2, a3, l, sb, jbase);
    }

    // last split also scores the 4 freshly-projected (already roped) keys
    if (ks == 7 && w < 2) {
        int qq = 2 * w + g;               // 0..3
        int jj = KVLEN + 2 * w;           // pair base
        const float* krp = g_knew + (((b * NHK + (h >> 2)) * QQN) + qq) * HD;
        float4 krA = *(const float4*)(krp + d0);
        float4 krB = *(const float4*)(krp + d0 + 4);
        float a0 = dot8(krA, krB, qA[0], qB[0]);
        float a1 = dot8(krA, krB, qA[1], qB[1]);
        float a2 = dot8(krA, krB, qA[2], qB[2]);
        float a3 = dot8(krA, krB, qA[3], qB[3]);
        reduce_store_2key(a0, a1, a2, a3, l, sb, jj);
    }
}

// ---------------- 4) exact top-410 radix select + softmax + V gather --------
__device__ __forceinline__ unsigned fkey(float f) {
    unsigned u = __float_as_uint(f);
    return (u & 0x80000000u) ? ~u : (u | 0x80000000u);  // order-preserving
}

__global__ void __launch_bounds__(256) select_kernel(const float* __restrict__ vcache) {
    __shared__ float sc[STOT];
    __shared__ unsigned hist[256];
    __shared__ int   s_idx[512];
    __shared__ float s_w[512];
    __shared__ float red[256];
    __shared__ float acc2[2][HD];
    __shared__ int s_bin, s_rem, s_cnt;

    int blk = blockIdx.x;           // 0..255
    int qq = blk & 3;
    int h  = (blk >> 2) & 31;
    int b  = blk >> 7;
    int bh = b * NH + h;
    int tid = threadIdx.x;
    int lane = tid & 31;

    const float* srow = g_scores + ((size_t)bh * QQN + qq) * STOT;

    float lmax = -3.402823466e38f;
    for (int i = tid; i < STOT; i += 256) {
        float v = srow[i];
        sc[i] = v;
        lmax = fmaxf(lmax, v);
    }
    red[tid] = lmax;
    __syncthreads();
    for (int o = 128; o; o >>= 1) {
        if (tid < o) red[tid] = fmaxf(red[tid], red[tid + o]);
        __syncthreads();
    }
    float rmax = red[0];
    __syncthreads();

    // radix select the RSEL-th largest key (exact); warp-aggregated histogram
    unsigned prefix = 0;
    int remaining = RSEL;
    for (int shift = 24; shift >= 0; shift -= 8) {
        hist[tid] = 0;
        __syncthreads();
        unsigned pmask = (shift == 24) ? 0u : (0xFFFFFFFFu << (shift + 8));
        for (int i = tid; i < 4352; i += 256) {   // padded: all warps full
            unsigned k = (i < STOT) ? fkey(sc[i]) : 0u;
            bool ok = (i < STOT) && ((k & pmask) == prefix);
            unsigned act = __ballot_sync(0xffffffffu, ok);
            if (ok) {
                int bin = (int)((k >> shift) & 255u);
                unsigned peers = __match_any_sync(act, bin);
                if (lane == __ffs(peers) - 1)
                    atomicAdd(&hist[bin], (unsigned)__popc(peers));
            }
        }
        __syncthreads();
        #pragma unroll
        for (int off = 1; off < 256; off <<= 1) {
            unsigned v = hist[tid];
            unsigned ad = (tid + off < 256) ? hist[tid + off] : 0u;
            __syncthreads();
            hist[tid] = v + ad;
            __syncthreads();
        }
        unsigned sfx = hist[tid];
        unsigned nxt = (tid < 255) ? hist[tid + 1] : 0u;
        if ((int)sfx >= remaining && (int)nxt < remaining) {
            s_bin = tid;
            s_rem = remaining - (int)nxt;
        }
        __syncthreads();
        prefix |= ((unsigned)s_bin) << shift;
        remaining = s_rem;
        __syncthreads();
    }
    unsigned thr = prefix;

    if (tid == 0) s_cnt = 0;
    __syncthreads();
    const float inv_sqrt = 0.08838834764831845f;  // 1/sqrt(128)
    float lden = 0.f;
    for (int i = tid; i < 4352; i += 256) {
        bool sel = (i < STOT) && (fkey(sc[i]) >= thr);
        unsigned bal = __ballot_sync(0xffffffffu, sel);
        int nsel = __popc(bal);
        int base = 0;
        if (nsel) {
            int ldr = __ffs(bal) - 1;
            if (lane == ldr) base = atomicAdd(&s_cnt, nsel);
            base = __shfl_sync(0xffffffffu, base, ldr);
        }
        if (sel) {
            int pos = base + __popc(bal & ((1u << lane) - 1u));
            float wgt = expf((sc[i] - rmax) * inv_sqrt);
            lden += wgt;
            if (pos < 512) { s_idx[pos] = i; s_w[pos] = wgt; }
        }
    }
    red[tid] = lden;
    __syncthreads();
    for (int o = 128; o; o >>= 1) {
        if (tid < o) red[tid] += red[tid + o];
        __syncthreads();
    }
    float den = red[0];
    __syncthreads();
    int n = s_cnt < 512 ? s_cnt : 512;

    // gather V (coalesced 512B rows), two key-halves in parallel, ILP 4
    int half = tid >> 7;
    int d = tid & 127;
    const float* vb = vcache + (size_t)bh * KVLEN * HD;
    const float* vn = g_vnew + (((b * NHK + (h >> 2)) * QQN)) * HD;
    float a = 0.f;
    #pragma unroll 4
    for (int i = half; i < n; i += 2) {
        int j = s_idx[i];
        float wv = s_w[i];
        float v = (j < KVLEN) ? vb[(size_t)j * HD + d]
                              : vn[(j - KVLEN) * HD + d];
        a = fmaf(wv, v, a);
    }
    acc2[half][d] = a;
    __syncthreads();
    if (tid < HD) {
        float o = (acc2[0][tid] + acc2[1][tid]) / den;
        g_attn[((size_t)(b * QQN + qq)) * DMODEL + h * HD + tid] = o;
    }
}

// ---------------- 5) output projection (split-K partials) ----------------
__global__ void __launch_bounds__(128) oproj_kernel(const float* __restrict__ Wo) {
    __shared__ float hs[8][128];
    int tile = blockIdx.x;   // 0..7 (512 cols each)
    int kc   = blockIdx.y;   // 0..31 (chunk 128)
    int tid  = threadIdx.x;  // 0..127
    int k0   = kc * 128;

    for (int i = tid; i < 256; i += 128) {
        int f = i * 4;
        int m = f >> 7;
        int d = f & 127;
        *(float4*)&hs[m][d] = *(const float4*)&g_attn[m * DMODEL + k0 + d];
    }
    __syncthreads();

    int col = tile * 512 + tid * 4;
    const float* Wp = Wo + (size_t)k0 * DMODEL + col;

    float4 a[8];
    #pragma unroll
    for (int m = 0; m < 8; m++) { a[m].x = 0.f; a[m].y = 0.f; a[m].z = 0.f; a[m].w = 0.f; }

    #pragma unroll 4
    for (int dd = 0; dd < 128; dd++) {
        float4 wv = *(const float4*)(Wp + (size_t)dd * DMODEL);
        #pragma unroll
        for (int m = 0; m < 8; m++) {
            float h = hs[m][dd];
            a[m].x = fmaf(h, wv.x, a[m].x);
            a[m].y = fmaf(h, wv.y, a[m].y);
            a[m].z = fmaf(h, wv.z, a[m].z);
            a[m].w = fmaf(h, wv.w, a[m].w);
        }
    }
    #pragma unroll
    for (int m = 0; m < 8; m++)
        *(float4*)&g_op[kc][m][col] = a[m];
}

__global__ void __launch_bounds__(256) oreduce_kernel(float* __restrict__ out) {
    int idx = blockIdx.x * blockDim.x + threadIdx.x;   // 8192 threads
    if (idx >= 8 * (DMODEL / 4)) return;
    int c4 = (idx % (DMODEL / 4)) * 4;
    int m  = idx / (DMODEL / 4);
    float4 s = make_float4(0.f, 0.f, 0.f, 0.f);
    #pragma unroll
    for (int k = 0; k < OKC; k++) {
        float4 v = *(const float4*)&g_op[k][m][c4];
        s.x += v.x; s.y += v.y; s.z += v.z; s.w += v.w;
    }
    *(float4*)&out[(size_t)m * DMODEL + c4] = s;
}

// ---------------- launch ----------------
extern "C" void kernel_launch(void* const* d_in, const int* in_sizes, int n_in,
                              void* d_out, int out_size) {
    const float* hidden = (const float*)d_in[0];
    const float* kcache = (const float*)d_in[1];
    const float* vcache = (const float*)d_in[2];
    const float* Wq     = (const float*)d_in[3];
    const float* Wk     = (const float*)d_in[4];
    const float* Wv     = (const float*)d_in[5];
    const float* Wo     = (const float*)d_in[6];
    float* out = (float*)d_out;

    rope_proj_kernel<<<ROPE_BLOCKS + PROJ_TILES * PROJ_KC, 256>>>(hidden, Wq, Wk, Wv);
    proj_reduce_kernel<<<(8 * (NCTOT / 4) + 255) / 256, 256>>>();
    score_kernel<<<dim3(64, 8), 256>>>(kcache);
    select_kernel<<<256, 256>>>(vcache);
    oproj_kernel<<<dim3(8, 32), 128>>>(Wo);
    oreduce_kernel<<<(8 * (DMODEL / 4) + 255) / 256, 256>>>(out);
}

// round 14
// speedup vs baseline: 1.3409x; 1.3409x over previous
#include <cuda_runtime.h>
#include <math.h>
#include <stdint.h>

// ---------------- problem constants ----------------
#define BB    2
#define QQN   4
#define NH    32
#define NHK   8
#define HD    128
#define DMODEL 4096
#define KVLEN 4096
#define STOT  4100          // KVLEN + QQN
#define RSEL  410           // max(128, 4100 - int(4100*0.9))
#define NCTOT 6144          // 4096 (q) + 1024 (k) + 1024 (v)
#define PKC   32            // proj split-K chunks (chunk = 128)
#define OKC   64            // out-proj split-K chunks (chunk = 64)

// ---------------- device scratch ----------------
__device__ float g_invf[64];
__device__ float g_cos[STOT * 64];
__device__ float g_sin[STOT * 64];
__device__ float g_pp[PKC][8][NCTOT];          // projection partials
__device__ float g_qrope[BB * NH * QQN * HD];  // roped queries
__device__ float g_knew[BB * NHK * QQN * HD];  // roped new keys
__device__ float g_vnew[BB * NHK * QQN * HD];  // new values (raw)
__device__ float g_scores[(size_t)BB * NH * QQN * STOT];
__device__ float g_attn[BB * QQN * DMODEL];    // [b][q][h*HD+d]
__device__ float g_op[OKC][8][DMODEL];         // out-proj partials

// ---------------- 1) rope tables (numerics: identical fp32 chain) -------------
__global__ void invf_kernel() {
    int j = threadIdx.x;
    if (j < 64) {
        float expo = (float)(2 * j) / 128.0f;   // exact
        g_invf[j] = 1.0f / powf(10000.0f, expo);
    }
}

__global__ void rope_table_kernel() {
    int i = blockIdx.x * blockDim.x + threadIdx.x;
    if (i >= STOT * 64) return;
    int p = i >> 6;
    float invf = g_invf[i & 63];
    float ang = (float)p * invf;
    g_cos[i] = cosf(ang);
    g_sin[i] = sinf(ang);
}

// ---------------- 2) fused QKV projection (split-K partials) ----------------
__global__ void __launch_bounds__(128) proj_kernel(
        const float* __restrict__ hidden,
        const float* __restrict__ Wq,
        const float* __restrict__ Wk,
        const float* __restrict__ Wv) {
    __shared__ float hs[8][128];
    int tile = blockIdx.x;   // 0..11
    int kc   = blockIdx.y;   // 0..31
    int tid  = threadIdx.x;  // 0..127
    int k0   = kc * 128;

    for (int i = tid; i < 256; i += 128) {
        int f = i * 4;
        int m = f >> 7;
        int d = f & 127;
        *(float4*)&hs[m][d] = *(const float4*)&hidden[m * DMODEL + k0 + d];
    }
    __syncthreads();

    const float* W;
    int ld, colbase;
    if (tile < 8)       { W = Wq; ld = 4096; colbase = tile * 512; }
    else if (tile < 10) { W = Wk; ld = 1024; colbase = tile * 512 - 4096; }
    else                { W = Wv; ld = 1024; colbase = tile * 512 - 5120; }

    int wcol = colbase + tid * 4;
    const float* Wp = W + (size_t)k0 * ld + wcol;

    float4 a[8];
    #pragma unroll
    for (int m = 0; m < 8; m++) { a[m].x = 0.f; a[m].y = 0.f; a[m].z = 0.f; a[m].w = 0.f; }

    #pragma unroll 8
    for (int d = 0; d < 128; d++) {
        float4 wv = *(const float4*)(Wp + (size_t)d * ld);
        #pragma unroll
        for (int m = 0; m < 8; m++) {
            float h = hs[m][d];
            a[m].x = fmaf(h, wv.x, a[m].x);
            a[m].y = fmaf(h, wv.y, a[m].y);
            a[m].z = fmaf(h, wv.z, a[m].z);
            a[m].w = fmaf(h, wv.w, a[m].w);
        }
    }

    int gc = tile * 512 + tid * 4;
    #pragma unroll
    for (int m = 0; m < 8; m++)
        *(float4*)&g_pp[kc][m][gc] = a[m];
}

// ---------------- 3) reduce partials + rope q / new-k ----------------
__global__ void proj_reduce_kernel() {
    int idx = blockIdx.x * blockDim.x + threadIdx.x;
    if (idx >= 8 * NCTOT) return;
    int c = idx % NCTOT;
    int m = idx / NCTOT;
    float s = 0.f;
    #pragma unroll
    for (int k = 0; k < PKC; k++) s += g_pp[k][m][c];

    int b  = m >> 2;
    int qq = m & 3;

    if (c < 5120) {  // q or k_new: apply rope at position 4096+qq
        int d  = c & 127;
        int pc = (d < 64) ? c + 64 : c - 64;
        float s2 = 0.f;
        #pragma unroll
        for (int k = 0; k < PKC; k++) s2 += g_pp[k][m][pc];
        int p = KVLEN + qq;
        float ct = g_cos[p * 64 + (d & 63)];
        float st = g_sin[p * 64 + (d & 63)];
        float rot = (d < 64) ? -s2 : s2;
        float r = s * ct + rot * st;
        if (c < 4096) {
            int h = c >> 7;
            g_qrope[(((b * NH + h) * QQN) + qq) * HD + d] = r;
        } else {
            int hk = (c - 4096) >> 7;
            g_knew[(((b * NHK + hk) * QQN) + qq) * HD + d] = r;
        }
    } else {         // v_new: raw copy
        int d  = c & 127;
        int hk = (c - 5120) >> 7;
        g_vnew[(((b * NHK + hk) * QQN) + qq) * HD + d] = s;
    }
}

// ---------------- 4) draft scores -------------------------------------------
// 16 lanes per key, 2 keys per warp. Each lane owns 8 contiguous dims (2 float4).
// RoPE partner (dim +-64) sits at lane^8 (4 shfls/key). Transposed reduction:
// xor4/xor8 on 4 query-accs, pick acc[(l>>2)&3], xor1/xor2 (5 shfls/key).
__device__ __forceinline__ void reduce_store_2key(
    float acc0, float acc1, float acc2, float acc3,
    int l, float* __restrict__ sb, int jbase)
{
    acc0 += __shfl_xor_sync(0xffffffffu, acc0, 4);
    acc1 += __shfl_xor_sync(0xffffffffu, acc1, 4);
    acc2 += __shfl_xor_sync(0xffffffffu, acc2, 4);
    acc3 += __shfl_xor_sync(0xffffffffu, acc3, 4);
    acc0 += __shfl_xor_sync(0xffffffffu, acc0, 8);
    acc1 += __shfl_xor_sync(0xffffffffu, acc1, 8);
    acc2 += __shfl_xor_sync(0xffffffffu, acc2, 8);
    acc3 += __shfl_xor_sync(0xffffffffu, acc3, 8);
    // lane now holds acc[qi] = partial over lanes {l, l^4, l^8, l^12} (fixed l&3)
    int qi = (l >> 2) & 3;
    float w = (qi == 0) ? acc0 : (qi == 1) ? acc1 : (qi == 2) ? acc2 : acc3;
    w += __shfl_xor_sync(0xffffffffu, w, 1);
    w += __shfl_xor_sync(0xffffffffu, w, 2);
    if ((l & 3) == 0)
        sb[(size_t)qi * STOT + jbase + (l >> 4)] = w;
}

__device__ __forceinline__ float dot8(float4 a0, float4 a1, float4 b0, float4 b1) {
    float s = a0.x * b0.x;
    s = fmaf(a0.y, b0.y, s);
    s = fmaf(a0.z, b0.z, s);
    s = fmaf(a0.w, b0.w, s);
    s = fmaf(a1.x, b1.x, s);
    s = fmaf(a1.y, b1.y, s);
    s = fmaf(a1.z, b1.z, s);
    s = fmaf(a1.w, b1.w, s);
    return s;
}

__global__ void __launch_bounds__(256) score_kernel(const float* __restrict__ kcache) {
    int bh = blockIdx.x;              // 0..63
    int b  = bh >> 5;
    int h  = bh & 31;
    int ks = blockIdx.y;              // 0..7 -> 512 cache keys each
    int tid = threadIdx.x;
    int w = tid >> 5;
    int l = tid & 31;
    int g  = l >> 4;                  // which of the warp's 2 keys
    int sl = l & 15;                  // sublane within key group
    int d0 = sl * 8;                  // first of this lane's 8 dims
    int cidx = (l & 7) * 8;           // cos/sin base index (d0 & 63)
    float sg = (sl < 8) ? -1.0f : 1.0f;

    // q: 4 queries x 8 dims, registers (no LDS/LDG in loop)
    const float* qb = g_qrope + (size_t)bh * QQN * HD;
    float4 qA[4], qB[4];
    #pragma unroll
    for (int qi = 0; qi < 4; qi++) {
        qA[qi] = *(const float4*)(qb + qi * HD + d0);
        qB[qi] = *(const float4*)(qb + qi * HD + d0 + 4);
    }

    const float* kb = kcache + (size_t)bh * KVLEN * HD;
    float* sb = g_scores + (size_t)bh * QQN * STOT;

    int j0 = ks * 512;
    // warp handles keys jbase = j0 + 2w + 16t (t = 0..31), key pair {jbase, jbase+1}
    int jbase = j0 + 2 * w;

    // 1-deep prefetch pipeline
    const float* kp = kb + (size_t)(jbase + g) * HD + d0;
    const float* cp = &g_cos[(jbase + g) * 64 + cidx];
    const float* sp = &g_sin[(jbase + g) * 64 + cidx];
    float4 kA = *(const float4*)kp;
    float4 kB = *(const float4*)(kp + 4);
    float4 cA = *(const float4*)cp;
    float4 cB = *(const float4*)(cp + 4);
    float4 sA = *(const float4*)sp;
    float4 sB = *(const float4*)(sp + 4);

    #pragma unroll 2
    for (int t = 0; t < 32; t++) {
        int jn = jbase + 16;
        float4 kA2 = kA, kB2 = kB, cA2 = cA, cB2 = cB, sA2 = sA, sB2 = sB;
        if (t < 31) {
            const float* kp2 = kb + (size_t)(jn + g) * HD + d0;
            const float* cp2 = &g_cos[(jn + g) * 64 + cidx];
            const float* sp2 = &g_sin[(jn + g) * 64 + cidx];
            kA2 = *(const float4*)kp2;
            kB2 = *(const float4*)(kp2 + 4);
            cA2 = *(const float4*)cp2;
            cB2 = *(const float4*)(cp2 + 4);
            sA2 = *(const float4*)sp2;
            sB2 = *(const float4*)(sp2 + 4);
        }

        // RoPE partner exchange (dim +-64 lives at lane^8)
        float pAx = __shfl_xor_sync(0xffffffffu, kA.x, 8);
        float pAy = __shfl_xor_sync(0xffffffffu, kA.y, 8);
        float pAz = __shfl_xor_sync(0xffffffffu, kA.z, 8);
        float pAw = __shfl_xor_sync(0xffffffffu, kA.w, 8);
        float pBx = __shfl_xor_sync(0xffffffffu, kB.x, 8);
        float pBy = __shfl_xor_sync(0xffffffffu, kB.y, 8);
        float pBz = __shfl_xor_sync(0xffffffffu, kB.z, 8);
        float pBw = __shfl_xor_sync(0xffffffffu, kB.w, 8);

        float4 krA, krB;
        krA.x = fmaf(kA.x, cA.x, sg * pAx * sA.x);
        krA.y = fmaf(kA.y, cA.y, sg * pAy * sA.y);
        krA.z = fmaf(kA.z, cA.z, sg * pAz * sA.z);
        krA.w = fmaf(kA.w, cA.w, sg * pAw * sA.w);
        krB.x = fmaf(kB.x, cB.x, sg * pBx * sB.x);
        krB.y = fmaf(kB.y, cB.y, sg * pBy * sB.y);
        krB.z = fmaf(kB.z, cB.z, sg * pBz * sB.z);
        krB.w = fmaf(kB.w, cB.w, sg * pBw * sB.w);

        float a0 = dot8(krA, krB, qA[0], qB[0]);
        float a1 = dot8(krA, krB, qA[1], qB[1]);
        float a2 = dot8(krA, krB, qA[2], qB[2]);
        float a3 = dot8(krA, krB, qA[3], qB[3]);
        reduce_store_2key(a0, a1, a2, a3, l, sb, jbase);

        kA = kA2; kB = kB2; cA = cA2; cB = cB2; sA = sA2; sB = sB2;
        jbase = jn;
    }

    // last split also scores the 4 freshly-projected (already roped) keys
    if (ks == 7 && w < 2) {
        int qq = 2 * w + g;               // 0..3
        int jj = KVLEN + 2 * w;           // pair base
        const float* krp = g_knew + (((b * NHK + (h >> 2)) * QQN) + qq) * HD;
        float4 krA = *(const float4*)(krp + d0);
        float4 krB = *(const float4*)(krp + d0 + 4);
        float a0 = dot8(krA, krB, qA[0], qB[0]);
        float a1 = dot8(krA, krB, qA[1], qB[1]);
        float a2 = dot8(krA, krB, qA[2], qB[2]);
        float a3 = dot8(krA, krB, qA[3], qB[3]);
        reduce_store_2key(a0, a1, a2, a3, l, sb, jj);
    }
}

// ---------------- 5) exact top-410 radix select + softmax + V gather --------
// 512 threads/block: halves every smem scan, doubles warp parallelism across
// the ~34 barriers, and quadruples the independent V-row streams (occ fix).
__device__ __forceinline__ unsigned fkey(float f) {
    unsigned u = __float_as_uint(f);
    return (u & 0x80000000u) ? ~u : (u | 0x80000000u);  // order-preserving
}

__global__ void __launch_bounds__(512) select_kernel(const float* __restrict__ vcache) {
    __shared__ float sc[STOT];
    __shared__ unsigned hist[256];
    __shared__ int   s_idx[512];
    __shared__ float s_w[512];
    __shared__ float red[512];
    __shared__ float acc4[4][HD];
    __shared__ int s_bin, s_rem, s_cnt;

    int blk = blockIdx.x;           // 0..255
    int qq = blk & 3;
    int h  = (blk >> 2) & 31;
    int b  = blk >> 7;
    int bh = b * NH + h;
    int tid = threadIdx.x;
    int lane = tid & 31;

    const float* srow = g_scores + ((size_t)bh * QQN + qq) * STOT;

    float lmax = -3.402823466e38f;
    for (int i = tid; i < STOT; i += 512) {
        float v = srow[i];
        sc[i] = v;
        lmax = fmaxf(lmax, v);
    }
    red[tid] = lmax;
    __syncthreads();
    for (int o = 256; o; o >>= 1) {
        if (tid < o) red[tid] = fmaxf(red[tid], red[tid + o]);
        __syncthreads();
    }
    float rmax = red[0];
    __syncthreads();

    // radix select the RSEL-th largest key (exact); warp-aggregated histogram
    unsigned prefix = 0;
    int remaining = RSEL;
    for (int shift = 24; shift >= 0; shift -= 8) {
        if (tid < 256) hist[tid] = 0;
        __syncthreads();
        unsigned pmask = (shift == 24) ? 0u : (0xFFFFFFFFu << (shift + 8));
        for (int i = tid; i < 4608; i += 512) {   // padded: all warps full
            unsigned k = (i < STOT) ? fkey(sc[i]) : 0u;
            bool ok = (i < STOT) && ((k & pmask) == prefix);
            unsigned act = __ballot_sync(0xffffffffu, ok);
            if (ok) {
                int bin = (int)((k >> shift) & 255u);
                unsigned peers = __match_any_sync(act, bin);
                if (lane == __ffs(peers) - 1)
                    atomicAdd(&hist[bin], (unsigned)__popc(peers));
            }
        }
        __syncthreads();
        // parallel inclusive suffix sum (Hillis-Steele) over 256 bins
        #pragma unroll
        for (int off = 1; off < 256; off <<= 1) {
            unsigned v = 0, ad = 0;
            if (tid < 256) {
                v = hist[tid];
                ad = (tid + off < 256) ? hist[tid + off] : 0u;
            }
            __syncthreads();
            if (tid < 256) hist[tid] = v + ad;
            __syncthreads();
        }
        if (tid < 256) {
            unsigned sfx = hist[tid];
            unsigned nxt = (tid < 255) ? hist[tid + 1] : 0u;
            if ((int)sfx >= remaining && (int)nxt < remaining) {
                s_bin = tid;
                s_rem = remaining - (int)nxt;
            }
        }
        __syncthreads();
        prefix |= ((unsigned)s_bin) << shift;
        remaining = s_rem;
        __syncthreads();
    }
    unsigned thr = prefix;

    if (tid == 0) s_cnt = 0;
    __syncthreads();
    const float inv_sqrt = 0.08838834764831845f;  // 1/sqrt(128)
    float lden = 0.f;
    for (int i = tid; i < 4608; i += 512) {
        bool sel = (i < STOT) && (fkey(sc[i]) >= thr);
        unsigned bal = __ballot_sync(0xffffffffu, sel);
        int nsel = __popc(bal);
        int base = 0;
        if (nsel) {
            int ldr = __ffs(bal) - 1;
            if (lane == ldr) base = atomicAdd(&s_cnt, nsel);
            base = __shfl_sync(0xffffffffu, base, ldr);
        }
        if (sel) {
            int pos = base + __popc(bal & ((1u << lane) - 1u));
            float wgt = expf((sc[i] - rmax) * inv_sqrt);
            lden += wgt;
            if (pos < 512) { s_idx[pos] = i; s_w[pos] = wgt; }
        }
    }
    red[tid] = lden;
    __syncthreads();
    for (int o = 256; o; o >>= 1) {
        if (tid < o) red[tid] += red[tid + o];
        __syncthreads();
    }
    float den = red[0];
    __syncthreads();
    int n = s_cnt < 512 ? s_cnt : 512;

    // gather V (coalesced 512B rows), FOUR key-quarters in parallel, ILP 4
    int quarter = tid >> 7;         // 0..3
    int d = tid & 127;
    const float* vb = vcache + (size_t)bh * KVLEN * HD;
    const float* vn = g_vnew + (((b * NHK + (h >> 2)) * QQN)) * HD;
    float a = 0.f;
    #pragma unroll 4
    for (int i = quarter; i < n; i += 4) {
        int j = s_idx[i];
        float wv = s_w[i];
        float v = (j < KVLEN) ? vb[(size_t)j * HD + d]
                              : vn[(j - KVLEN) * HD + d];
        a = fmaf(wv, v, a);
    }
    acc4[quarter][d] = a;
    __syncthreads();
    if (tid < HD) {
        float o = ((acc4[0][tid] + acc4[1][tid]) + (acc4[2][tid] + acc4[3][tid])) / den;
        g_attn[((size_t)(b * QQN + qq)) * DMODEL + h * HD + tid] = o;
    }
}

// ---------------- 6) output projection (split-K partials) ----------------
__global__ void __launch_bounds__(128) oproj_kernel(const float* __restrict__ Wo) {
    __shared__ float hs[8][64];
    int tile = blockIdx.x;   // 0..7 (512 cols each)
    int kc   = blockIdx.y;   // 0..63 (chunk 64)
    int tid  = threadIdx.x;  // 0..127
    int k0   = kc * 64;

    {
        int f = tid * 4;
        int m = f >> 6;
        int d = f & 63;
        *(float4*)&hs[m][d] = *(const float4*)&g_attn[m * DMODEL + k0 + d];
    }
    __syncthreads();

    int col = tile * 512 + tid * 4;
    const float* Wp = Wo + (size_t)k0 * DMODEL + col;

    float4 a[8];
    #pragma unroll
    for (int m = 0; m < 8; m++) { a[m].x = 0.f; a[m].y = 0.f; a[m].z = 0.f; a[m].w = 0.f; }

    #pragma unroll 8
    for (int dd = 0; dd < 64; dd++) {
        float4 wv = *(const float4*)(Wp + (size_t)dd * DMODEL);
        #pragma unroll
        for (int m = 0; m < 8; m++) {
            float h = hs[m][dd];
            a[m].x = fmaf(h, wv.x, a[m].x);
            a[m].y = fmaf(h, wv.y, a[m].y);
            a[m].z = fmaf(h, wv.z, a[m].z);
            a[m].w = fmaf(h, wv.w, a[m].w);
        }
    }
    #pragma unroll
    for (int m = 0; m < 8; m++)
        *(float4*)&g_op[kc][m][col] = a[m];
}

__global__ void oreduce_kernel(float* __restrict__ out) {
    int idx = blockIdx.x * blockDim.x + threadIdx.x;
    if (idx >= 8 * DMODEL) return;
    int c = idx & 4095;
    int m = idx >> 12;
    float s = 0.f;
    #pragma unroll
    for (int k = 0; k < OKC; k++) s += g_op[k][m][c];
    out[(size_t)m * DMODEL + c] = s;
}

// ---------------- launch ----------------
extern "C" void kernel_launch(void* const* d_in, const int* in_sizes, int n_in,
                              void* d_out, int out_size) {
    const float* hidden = (const float*)d_in[0];
    const float* kcache = (const float*)d_in[1];
    const float* vcache = (const float*)d_in[2];
    const float* Wq     = (const float*)d_in[3];
    const float* Wk     = (const float*)d_in[4];
    const float* Wv     = (const float*)d_in[5];
    const float* Wo     = (const float*)d_in[6];
    float* out = (float*)d_out;

    invf_kernel<<<1, 64>>>();
    rope_table_kernel<<<(STOT * 64 + 255) / 256, 256>>>();
    proj_kernel<<<dim3(12, 32), 128>>>(hidden, Wq, Wk, Wv);
    proj_reduce_kernel<<<(8 * NCTOT + 255) / 256, 256>>>();
    score_kernel<<<dim3(64, 8), 256>>>(kcache);
    select_kernel<<<256, 512>>>(vcache);
    oproj_kernel<<<dim3(8, 64), 128>>>(Wo);
    oreduce_kernel<<<(8 * DMODEL + 255) / 256, 256>>>(out);
}